// round 14
// baseline (speedup 1.0000x reference)
#include <cuda_runtime.h>
#include <cuda_bf16.h>
#include <stdint.h>

#define NTH  512
#define TP   128
#define EXP  8
#define HDIM 64
#define DXX  63
#define DVV  27
#define KK1  78          // k-pairs for W_r1 (155 -> 156 padded)

typedef unsigned long long ull;

// ---- global scratch ----
__device__ __align__(16) float         g_Wenc[32 * 128 * 2];          // k-pair packed enc weights
__device__ __align__(16) __nv_bfloat16 g_WT[EXP * 2 * 128 * 136];     // [e][hi/mid][n=128][k=136pad]
__device__ __align__(16) float         g_Wr1[EXP * KK1 * 64 * 2];

// ---- shared memory byte offsets ----
#define SM_AH    0          // A_hi bf16 [128][136] (s_h[128][66]f overlays after experts)
#define SM_AM    34816      // A_mid
#define SM_BH    69632      // B_hi  [128][136] (current expert)
#define SM_BM    104448     // B_mid
#define SM_SHB   139264     // winner shape ull [64 kp][129]  (x_tp [32][258]f overlays pre-experts)
#define SM_VD    205312     // vd [14][258]f
#define SM_G     219760     // gumbel [1024]f
#define SM_PART  223856     // sigma partials [4][128]f
#define SM_SBIAS 225904     // [128]f
#define SM_SIGW  226416     // [128]f
#define SM_BEXP  226928     // [128]f
#define SM_BSIG  227440     // [128]f
#define SM_UPD   227952     // [128]f
#define SM_MBAR  228464     // full mbarrier (8B)
#define SM_MBAR2 228472     // empty mbarrier (8B)
#define SM_WR2   228480     // W_r2 bf16 [8][64][3] = 3072B
#define SM_BR2   231552     // b_r2 [24]f = 96B
#define SM_TOTAL 231648

#define B_BYTES  69632u     // one expert's hi+mid B tiles

__device__ __forceinline__ void ffma2(ull& acc, ull a, ull b) {
    asm("fma.rn.f32x2 %0, %1, %2, %0;" : "+l"(acc) : "l"(a), "l"(b));
}
__device__ __forceinline__ float2 unpack2(ull v) {
    float2 f; asm("mov.b64 {%0, %1}, %2;" : "=f"(f.x), "=f"(f.y) : "l"(v)); return f;
}
__device__ __forceinline__ ull pack2(float a, float b) {
    ull r; asm("mov.b64 %0, {%1, %2};" : "=l"(r) : "f"(a), "f"(b)); return r;
}
__device__ __forceinline__ void ldsm4(uint32_t* r, uint32_t addr) {
    asm volatile("ldmatrix.sync.aligned.m8n8.x4.shared.b16 {%0,%1,%2,%3}, [%4];"
        : "=r"(r[0]), "=r"(r[1]), "=r"(r[2]), "=r"(r[3]) : "r"(addr));
}
__device__ __forceinline__ void mma16816(float* d, const uint32_t* a, const uint32_t* b) {
    asm volatile("mma.sync.aligned.m16n8k16.row.col.f32.bf16.bf16.f32 "
        "{%0,%1,%2,%3}, {%4,%5,%6,%7}, {%8,%9}, {%0,%1,%2,%3};"
        : "+f"(d[0]), "+f"(d[1]), "+f"(d[2]), "+f"(d[3])
        : "r"(a[0]), "r"(a[1]), "r"(a[2]), "r"(a[3]), "r"(b[0]), "r"(b[1]));
}
__device__ __forceinline__ void mbar_init(uint32_t a, uint32_t cnt) {
    asm volatile("mbarrier.init.shared.b64 [%0], %1;" :: "r"(a), "r"(cnt) : "memory");
}
__device__ __forceinline__ void mbar_arrive(uint32_t a) {
    asm volatile("mbarrier.arrive.shared.b64 _, [%0];" :: "r"(a) : "memory");
}
__device__ __forceinline__ void mbar_expect(uint32_t a, uint32_t bytes) {
    asm volatile("mbarrier.arrive.expect_tx.shared.b64 _, [%0], %1;" :: "r"(a), "r"(bytes) : "memory");
}
__device__ __forceinline__ void bulk_cp(uint32_t dst, const void* src, uint32_t bytes, uint32_t mbar) {
    asm volatile("cp.async.bulk.shared::cta.global.mbarrier::complete_tx::bytes [%0], [%1], %2, [%3];"
                 :: "r"(dst), "l"(src), "r"(bytes), "r"(mbar) : "memory");
}
#define MBAR_WAIT(addr, par) do { \
    uint32_t _m = (addr), _p = (par), _d; \
    asm volatile("{\n\t.reg .pred p;\n\tmbarrier.try_wait.parity.acquire.cta.shared::cta.b64 p, [%1], %2;\n\tselp.b32 %0, 1, 0, p;\n\t}" \
        : "=r"(_d) : "r"(_m), "r"(_p) : "memory"); \
    if (!_d) { \
        asm volatile("{\n\t.reg .pred P1;\n\tWL%=:\n\tmbarrier.try_wait.parity.acquire.cta.shared::cta.b64 P1, [%0], %1, 0x989680;\n\t@P1 bra.uni WD%=;\n\tbra.uni WL%=;\n\tWD%=:\n\t}" \
            :: "r"(_m), "r"(_p) : "memory"); \
    } } while (0)

// ---- JAX threefry2x32 (20 rounds) ----
__device__ __forceinline__ uint2 tf2x32(unsigned k0, unsigned k1, unsigned x0, unsigned x1) {
    unsigned ks2 = k0 ^ k1 ^ 0x1BD11BDAu;
    x0 += k0; x1 += k1;
#define TFR(r) { x0 += x1; x1 = (x1 << (r)) | (x1 >> (32 - (r))); x1 ^= x0; }
    TFR(13) TFR(15) TFR(26) TFR(6)
    x0 += k1;  x1 += ks2 + 1u;
    TFR(17) TFR(29) TFR(16) TFR(24)
    x0 += ks2; x1 += k0 + 2u;
    TFR(13) TFR(15) TFR(26) TFR(6)
    x0 += k0;  x1 += k1 + 3u;
    TFR(17) TFR(29) TFR(16) TFR(24)
    x0 += k1;  x1 += ks2 + 4u;
    TFR(13) TFR(15) TFR(26) TFR(6)
    x0 += ks2; x1 += k0 + 5u;
#undef TFR
    return make_uint2(x0, x1);
}

__global__ void prep_pack(const float* __restrict__ W_enc,
                          const float* __restrict__ W_sh,
                          const float* __restrict__ W_r1) {
    const int i = blockIdx.x * blockDim.x + threadIdx.x;
    if (i < 32 * 128 * 2) {
        const int j = i & 1, c = (i >> 1) & 127, kp = i >> 8;
        const int k = 2 * kp + j;
        g_Wenc[i] = (k < DXX) ? W_enc[k * 128 + c] : 0.f;
    }
    const int i2 = i - 32 * 128 * 2;
    if (i2 >= 0 && i2 < EXP * 16384) {
        const int e = i2 >> 14, r = i2 & 16383;
        const int k = r >> 7, c = r & 127;          // W_sh[e][k][c]
        const float val = W_sh[e * 16384 + k * 128 + c];
        const __nv_bfloat16 h = __float2bfloat16(val);
        const __nv_bfloat16 m = __float2bfloat16(val - __bfloat162float(h));
        g_WT[(e * 2 + 0) * (128 * 136) + c * 136 + k] = h;
        g_WT[(e * 2 + 1) * (128 * 136) + c * 136 + k] = m;
    }
    const int i3 = i - (32 * 128 * 2 + EXP * 16384);
    if (i3 >= 0 && i3 < EXP * KK1 * 128) {
        const int e = i3 / (KK1 * 128), r = i3 % (KK1 * 128);
        const int kp = r >> 7, c = (r >> 1) & 63, j = r & 1;
        const int k = 2 * kp + j;
        g_Wr1[i3] = (k < 155) ? W_r1[e * 155 * 64 + k * 64 + c] : 0.f;
    }
}

__global__ void __launch_bounds__(NTH, 1)
nerf_fused(const float* __restrict__ x,
           const float* __restrict__ b_enc,
           const float* __restrict__ b_sh,
           const float* __restrict__ w_sig, const float* __restrict__ b_sig,
           const float* __restrict__ b_r1,
           const float* __restrict__ W_r2,  const float* __restrict__ b_r2,
           float* __restrict__ out, int n)
{
    extern __shared__ char smc[];
    const int tid = threadIdx.x;
    const int n0  = blockIdx.x * TP;
    const int wp  = tid >> 5, l = tid & 31;
    const uint32_t sbase = (uint32_t)__cvta_generic_to_shared(smc);

    float* s_g    = (float*)(smc + SM_G);
    float* s_part = (float*)(smc + SM_PART);
    float* sbias  = (float*)(smc + SM_SBIAS);
    float* sigw   = (float*)(smc + SM_SIGW);
    float* sbexp  = (float*)(smc + SM_BEXP);
    float* sbsig  = (float*)(smc + SM_BSIG);
    float* s_upd  = (float*)(smc + SM_UPD);
    ull*   shb    = (ull*)(smc + SM_SHB);
    __nv_bfloat16* wr2s = (__nv_bfloat16*)(smc + SM_WR2);
    float* br2s   = (float*)(smc + SM_BR2);
    const uint32_t mbar  = sbase + SM_MBAR;
    const uint32_t mbar2 = sbase + SM_MBAR2;

    // ---------- init mbarriers + launch expert-0 B-tile bulk copy ----------
    if (tid == 0) {
        mbar_init(mbar, 1);
        mbar_init(mbar2, 16);          // "B buffer free" barrier: one arrive per warp
        mbar_expect(mbar, B_BYTES);
        bulk_cp(sbase + SM_BH, (const char*)g_WT, B_BYTES, mbar);
    }

    // ---------- Phase A: PE into x_tp (overlay on shb) / vd ----------
    if (tid < 384) {
        const int p = tid / 3, c = tid % 3;
        float xc = 0.f, vc = 0.f;
        if (n0 + p < n) {
            xc = x[(n0 + p) * 6 + c];
            vc = x[(n0 + p) * 6 + 3 + c];
        }
        float* xf = (float*)(smc + SM_SHB);
        float* vf = (float*)(smc + SM_VD);
#define PUTX(k, v) xf[((k) >> 1) * 258 + 2 * p + ((k) & 1)] = (v)
#define PUTV(k, v) vf[((k) >> 1) * 258 + 2 * p + ((k) & 1)] = (v)
        PUTX(c, xc);
        float f = 1.f;
#pragma unroll
        for (int i = 0; i < 10; i++) {
            float sv, cv; sincosf(f * xc, &sv, &cv);
            PUTX(3 + 3 * i + c, sv);
            PUTX(33 + 3 * i + c, cv);
            f *= 2.f;
        }
        PUTV(c, vc);
        f = 1.f;
#pragma unroll
        for (int i = 0; i < 4; i++) {
            float sv, cv; sincosf(f * vc, &sv, &cv);
            PUTV(3 + 3 * i + c, sv);
            PUTV(15 + 3 * i + c, cv);
            f *= 2.f;
        }
#undef PUTX
#undef PUTV
    }
    if (tid < 128) {
        ((float*)(smc + SM_SHB))[31 * 258 + 2 * tid + 1] = 0.f;  // x pad k=63
        ((float*)(smc + SM_VD))[13 * 258 + 2 * tid + 1] = 0.f;   // vd pad k=27
        sigw[tid] = w_sig[tid];
    }
    // ---------- stage W_r2 (bf16) + b_r2 into smem ----------
    for (int i = tid; i < EXP * HDIM * 3; i += NTH)
        wr2s[i] = __float2bfloat16(W_r2[i]);
    if (tid < 24) br2s[tid] = b_r2[tid];
    // ---------- Gumbel (JAX threefry, partitionable) ----------
#pragma unroll
    for (int idx = tid; idx < TP * EXP; idx += NTH) {
        const int p = idx >> 3;
        const unsigned f = (unsigned)(n0 + p) * 8u + (unsigned)(idx & 7);
        const uint2 r = tf2x32(0u, 42u, 0u, f);
        const unsigned bits = r.x ^ r.y;
        const float u = __uint_as_float((bits >> 9) | 0x3f800000u) - 1.0f;
        s_g[idx] = -logf(-logf(u + 1e-20f) + 1e-20f);
    }
    __syncthreads();

    // ---------- Phase B: y = relu(pe @ W_enc + b); 16 warps x 8 cols x 128 pts ----------
    {
        const int c0 = wp * 8;
        ull acc[8][4];
#pragma unroll
        for (int j = 0; j < 8; j++)
#pragma unroll
            for (int q = 0; q < 4; q++) acc[j][q] = 0ull;
        const ulonglong2* wE = (const ulonglong2*)g_Wenc + (c0 >> 1);
        const ull* xr = (const ull*)(smc + SM_SHB);
#pragma unroll 2
        for (int kp = 0; kp < 32; kp++) {
            ull a[4];
#pragma unroll
            for (int q = 0; q < 4; q++) a[q] = xr[kp * 129 + q * 32 + l];
            const ulonglong2 q0 = wE[kp * 64 + 0], q1 = wE[kp * 64 + 1];
            const ulonglong2 q2 = wE[kp * 64 + 2], q3 = wE[kp * 64 + 3];
            const ull w[8] = {q0.x, q0.y, q1.x, q1.y, q2.x, q2.y, q3.x, q3.y};
#pragma unroll
            for (int j = 0; j < 8; j++)
#pragma unroll
                for (int q = 0; q < 4; q++) ffma2(acc[j][q], a[q], w[j]);
        }
        __syncthreads();   // x_tp reads complete before shb-region reuse (winner stores)
#pragma unroll
        for (int j = 0; j < 8; j++) {
            const int col = c0 + j;
            const float bc = b_enc[col];
#pragma unroll
            for (int q = 0; q < 4; q++) {
                const float2 f2 = unpack2(acc[j][q]);
                const float v = fmaxf(f2.x + f2.y + bc, 0.f);
                const int p = l + 32 * q;
                const __nv_bfloat16 h = __float2bfloat16(v);
                const __nv_bfloat16 m = __float2bfloat16(v - __bfloat162float(h));
                *(__nv_bfloat16*)(smc + SM_AH + (p * 136 + col) * 2) = h;
                *(__nv_bfloat16*)(smc + SM_AM + (p * 136 + col) * 2) = m;
            }
        }
    }

    // ---------- MMA fragment address bases (warp grid 4m x 4n, tile 32x32) ----------
    const int wm = wp >> 2, wn = wp & 3;
    const int m0 = wm * 32, nn0 = wn * 32;
    const uint32_t aOff = ((m0 + (l & 15)) * 136 + (l >> 4) * 8) * 2;
    const uint32_t aH0 = sbase + SM_AH + aOff, aH1 = aH0 + 16 * 272;
    const uint32_t aM0 = sbase + SM_AM + aOff, aM1 = aM0 + 16 * 272;
    const uint32_t bOff = ((nn0 + (l & 7) + ((l >> 4) & 1) * 8) * 136 + ((l >> 3) & 1) * 8) * 2;
    const uint32_t bH0 = sbase + SM_BH + bOff, bH1 = bH0 + 16 * 272;
    const uint32_t bM0 = sbase + SM_BM + bOff, bM1 = bM0 + 16 * 272;

    float best_sc = 0.f, best_sig = 0.f;
    int best_e = 0;
    const float bsig0 = b_sig[0];

    if (tid < 128) sbias[tid] = b_sh[tid];
    __syncthreads();   // A tiles + sbias visible

    // ---------- Expert loop ----------
    for (int e = 0; e < EXP; e++) {
        MBAR_WAIT(mbar, e & 1);   // wait for this expert's B tiles

        float acc[2][4][4];
#pragma unroll
        for (int mf = 0; mf < 2; mf++)
#pragma unroll
            for (int nf = 0; nf < 4; nf++)
#pragma unroll
                for (int i = 0; i < 4; i++) acc[mf][nf][i] = 0.f;

#pragma unroll
        for (int kc = 0; kc < 8; kc++) {
            uint32_t ah[2][4], am[2][4], bh[2][4], bm[2][4];
            ldsm4(ah[0], aH0 + kc * 32);  ldsm4(ah[1], aH1 + kc * 32);
            ldsm4(am[0], aM0 + kc * 32);  ldsm4(am[1], aM1 + kc * 32);
            ldsm4(bh[0], bH0 + kc * 32);  ldsm4(bh[1], bH1 + kc * 32);
            ldsm4(bm[0], bM0 + kc * 32);  ldsm4(bm[1], bM1 + kc * 32);
#pragma unroll
            for (int mf = 0; mf < 2; mf++)
#pragma unroll
                for (int np = 0; np < 2; np++) {
                    mma16816(acc[mf][np*2+0], ah[mf], &bh[np][0]);
                    mma16816(acc[mf][np*2+1], ah[mf], &bh[np][2]);
                    mma16816(acc[mf][np*2+0], ah[mf], &bm[np][0]);
                    mma16816(acc[mf][np*2+1], ah[mf], &bm[np][2]);
                    mma16816(acc[mf][np*2+0], am[mf], &bh[np][0]);
                    mma16816(acc[mf][np*2+1], am[mf], &bh[np][2]);
                }
        }

        // B buffer now free for this warp: signal, and thread 0 launches next copy
        // as soon as all 16 warps have signalled (overlaps epilogue + gating).
        if (e < EXP - 1) {
            if (l == 0) mbar_arrive(mbar2);
            if (tid == 0) {
                MBAR_WAIT(mbar2, e & 1);
                mbar_expect(mbar, B_BYTES);
                bulk_cp(sbase + SM_BH, (const char*)g_WT + (size_t)(e + 1) * B_BYTES, B_BYTES, mbar);
            }
        }

        // epilogue: bias+relu into acc, sigma partials
        float part[4] = {0.f, 0.f, 0.f, 0.f};
#pragma unroll
        for (int mf = 0; mf < 2; mf++)
#pragma unroll
            for (int nf = 0; nf < 4; nf++) {
                const int c0 = nn0 + nf * 8 + (l & 3) * 2;
                const float b0 = sbias[c0], b1 = sbias[c0 + 1];
                const float w0 = sigw[c0],  w1 = sigw[c0 + 1];
                const float v00 = fmaxf(acc[mf][nf][0] + b0, 0.f);
                const float v01 = fmaxf(acc[mf][nf][1] + b1, 0.f);
                const float v10 = fmaxf(acc[mf][nf][2] + b0, 0.f);
                const float v11 = fmaxf(acc[mf][nf][3] + b1, 0.f);
                acc[mf][nf][0] = v00; acc[mf][nf][1] = v01;
                acc[mf][nf][2] = v10; acc[mf][nf][3] = v11;
                part[mf*2+0] += v00 * w0 + v01 * w1;
                part[mf*2+1] += v10 * w0 + v11 * w1;
            }
#pragma unroll
        for (int i = 0; i < 4; i++) {
            part[i] += __shfl_xor_sync(0xffffffffu, part[i], 1);
            part[i] += __shfl_xor_sync(0xffffffffu, part[i], 2);
        }
        if ((l & 3) == 0) {
#pragma unroll
            for (int mf = 0; mf < 2; mf++)
#pragma unroll
                for (int hf = 0; hf < 2; hf++)
                    s_part[wn * 128 + m0 + mf * 16 + (l >> 2) + hf * 8] = part[mf*2+hf];
        }
        __syncthreads();    // s_part ready

        if (tid < 128) {
            const float t = s_part[tid] + s_part[128 + tid] + s_part[256 + tid]
                          + s_part[384 + tid] + bsig0;
            const float sg = fmaxf(t, 0.f) + log1pf(expf(-fabsf(t)));  // softplus
            const float sc = logf(sg + 1e-10f) / 0.166667f + s_g[tid * 8 + e];
            const bool win = (e == 0) || (sc > best_sc);
            if (win) { best_sc = sc; best_sig = sg; best_e = e; }
            s_upd[tid] = win ? 1.f : 0.f;
        }
        __syncthreads();

        // winner shape store (transposed-pair layout for C3')
#pragma unroll
        for (int mf = 0; mf < 2; mf++) {
            const int rA = m0 + mf * 16 + (l >> 2);
            const bool wA = (s_upd[rA] != 0.f), wB = (s_upd[rA + 8] != 0.f);
#pragma unroll
            for (int nf = 0; nf < 4; nf++) {
                const int cp_i = wn * 16 + nf * 4 + (l & 3);
                if (wA) shb[cp_i * 129 + rA]     = pack2(acc[mf][nf][0], acc[mf][nf][1]);
                if (wB) shb[cp_i * 129 + rA + 8] = pack2(acc[mf][nf][2], acc[mf][nf][3]);
            }
        }
        if (tid < 128 && e < EXP - 1) sbias[tid] = b_sh[(e + 1) * 128 + tid];
        __syncthreads();
    }

    if (tid < 128) { sbexp[tid] = (float)best_e; sbsig[tid] = best_sig; }
    __syncthreads();

    // ---------- C3': h = relu([shape | vd] @ W_r1[winner] + b); 16 warps x 8 pts ----------
    float* s_h = (float*)(smc + SM_AH);   // overlay on dead A tiles: [128][66]
    {
        const int p0 = wp * 8;
        int we[8];
        const ulonglong2* w1[8];
        ull acc[8][2];
#pragma unroll
        for (int p = 0; p < 8; p++) {
            we[p] = (int)sbexp[p0 + p];
            w1[p] = (const ulonglong2*)(g_Wr1 + we[p] * (KK1 * 128)) + l;
            acc[p][0] = 0ull; acc[p][1] = 0ull;
        }
#pragma unroll 2
        for (int kp = 0; kp < 64; kp++) {
#pragma unroll
            for (int p = 0; p < 8; p++) {
                const ulonglong2 q = w1[p][kp * 32];
                const ull a = shb[kp * 129 + p0 + p];
                ffma2(acc[p][0], a, q.x);
                ffma2(acc[p][1], a, q.y);
            }
        }
        const ull* vdp = (const ull*)(smc + SM_VD);
#pragma unroll
        for (int kp = 64; kp < KK1; kp++) {
#pragma unroll
            for (int p = 0; p < 8; p++) {
                const ulonglong2 q = w1[p][kp * 32];
                const ull a = vdp[(kp - 64) * 129 + p0 + p];
                ffma2(acc[p][0], a, q.x);
                ffma2(acc[p][1], a, q.y);
            }
        }
#pragma unroll
        for (int p = 0; p < 8; p++) {
            const float2 bv = *(const float2*)(b_r1 + we[p] * HDIM + l * 2);
            const float2 f0 = unpack2(acc[p][0]), f1 = unpack2(acc[p][1]);
            const float h0 = fmaxf(f0.x + f0.y + bv.x, 0.f);
            const float h1 = fmaxf(f1.x + f1.y + bv.y, 0.f);
            *(ull*)(s_h + (p0 + p) * 66 + l * 2) = pack2(h0, h1);
        }
    }
    __syncthreads();

    // ---------- C4': rgb = sigmoid(h @ W_r2[winner] + b) -> out ----------
    if (tid < 384) {
        const int p = tid % 128, c = tid / 128;
        const int we = (int)sbexp[p];
        float acc = br2s[we * 3 + c];
        const float* hp = s_h + p * 66;
        const __nv_bfloat16* w2 = wr2s + we * (HDIM * 3) + c;
#pragma unroll
        for (int k = 0; k < HDIM; k++)
            acc = fmaf(hp[k], __bfloat162float(w2[k * 3]), acc);
        if (n0 + p < n)
            out[(n0 + p) * 4 + c] = 1.f / (1.f + expf(-acc));
    }
    if (tid < 128 && n0 + tid < n)
        out[(n0 + tid) * 4 + 3] = sbsig[tid];
}

extern "C" void kernel_launch(void* const* d_in, const int* in_sizes, int n_in,
                              void* d_out, int out_size) {
    const float* x     = (const float*)d_in[0];
    const float* W_enc = (const float*)d_in[1];
    const float* b_enc = (const float*)d_in[2];
    const float* W_sh  = (const float*)d_in[3];
    const float* b_sh  = (const float*)d_in[4];
    const float* w_sig = (const float*)d_in[5];
    const float* b_sig = (const float*)d_in[6];
    const float* W_r1  = (const float*)d_in[7];
    const float* b_r1  = (const float*)d_in[8];
    const float* W_r2  = (const float*)d_in[9];
    const float* b_r2  = (const float*)d_in[10];
    float* out = (float*)d_out;

    const int n = in_sizes[0] / 6;
    const int blocks = (n + TP - 1) / TP;

    const int prep_elems = 32*128*2 + EXP*16384 + EXP*KK1*128;
    prep_pack<<<(prep_elems + 255) / 256, 256>>>(W_enc, W_sh, W_r1);

    cudaFuncSetAttribute(nerf_fused, cudaFuncAttributeMaxDynamicSharedMemorySize, SM_TOTAL);
    nerf_fused<<<blocks, NTH, SM_TOTAL>>>(x, b_enc, b_sh, w_sig, b_sig,
                                          b_r1, W_r2, b_r2, out, n);
}

// round 15
// speedup vs baseline: 1.1982x; 1.1982x over previous
#include <cuda_runtime.h>
#include <cuda_bf16.h>
#include <stdint.h>

#define NTH  512
#define TP   128
#define EXP  8
#define HDIM 64
#define DXX  63
#define DVV  27
#define KK1  78          // k-pairs for W_r1 (155 -> 156 padded)

typedef unsigned long long ull;

// ---- global scratch ----
__device__ __align__(16) float         g_Wenc[32 * 128 * 2];          // k-pair packed enc weights
__device__ __align__(16) __nv_bfloat16 g_WT[EXP * 2 * 128 * 136];     // [e][hi/mid][n=128][k=136pad]
__device__ __align__(16) unsigned      g_Wr1b[EXP * KK1 * 64];        // bf16x2 (k-pair) per col

// ---- shared memory byte offsets ----
#define SM_AH    0          // A_hi bf16 [128][136] (s_h[128][66]f overlays after experts)
#define SM_AM    34816      // A_mid
#define SM_BH    69632      // B_hi  [128][136] (current expert)
#define SM_BM    104448     // B_mid
#define SM_SHB   139264     // winner shape ull [64 kp][129]  (x_tp [32][258]f overlays pre-experts)
#define SM_VD    205312     // vd [14][258]f
#define SM_G     219760     // gumbel [1024]f
#define SM_PART  223856     // sigma partials [4][128]f
#define SM_SBIAS 225904     // [128]f
#define SM_SIGW  226416     // [128]f
#define SM_BEXP  226928     // [128]f
#define SM_BSIG  227440     // [128]f
#define SM_UPD   227952     // [128]f
#define SM_MBAR  228464     // full mbarrier (8B)
#define SM_WR2   228480     // W_r2 bf16 [8][64][3] = 3072B
#define SM_BR2   231552     // b_r2 [24]f
#define SM_TOTAL 231648

#define B_BYTES  69632u     // one expert's hi+mid B tiles

__device__ __forceinline__ void ffma2(ull& acc, ull a, ull b) {
    asm("fma.rn.f32x2 %0, %1, %2, %0;" : "+l"(acc) : "l"(a), "l"(b));
}
__device__ __forceinline__ float2 unpack2(ull v) {
    float2 f; asm("mov.b64 {%0, %1}, %2;" : "=f"(f.x), "=f"(f.y) : "l"(v)); return f;
}
__device__ __forceinline__ ull pack2(float a, float b) {
    ull r; asm("mov.b64 %0, {%1, %2};" : "=l"(r) : "f"(a), "f"(b)); return r;
}
// bf16x2 (low = k0, high = k1) -> fp32-pair ull
__device__ __forceinline__ ull bf2w(unsigned u) {
    return ((ull)(u & 0xffff0000u) << 32) | (unsigned)(u << 16);
}
__device__ __forceinline__ void ldsm4(uint32_t* r, uint32_t addr) {
    asm volatile("ldmatrix.sync.aligned.m8n8.x4.shared.b16 {%0,%1,%2,%3}, [%4];"
        : "=r"(r[0]), "=r"(r[1]), "=r"(r[2]), "=r"(r[3]) : "r"(addr));
}
__device__ __forceinline__ void mma16816(float* d, const uint32_t* a, const uint32_t* b) {
    asm volatile("mma.sync.aligned.m16n8k16.row.col.f32.bf16.bf16.f32 "
        "{%0,%1,%2,%3}, {%4,%5,%6,%7}, {%8,%9}, {%0,%1,%2,%3};"
        : "+f"(d[0]), "+f"(d[1]), "+f"(d[2]), "+f"(d[3])
        : "r"(a[0]), "r"(a[1]), "r"(a[2]), "r"(a[3]), "r"(b[0]), "r"(b[1]));
}
__device__ __forceinline__ void mbar_init(uint32_t a, uint32_t cnt) {
    asm volatile("mbarrier.init.shared.b64 [%0], %1;" :: "r"(a), "r"(cnt) : "memory");
}
__device__ __forceinline__ void mbar_expect(uint32_t a, uint32_t bytes) {
    asm volatile("mbarrier.arrive.expect_tx.shared.b64 _, [%0], %1;" :: "r"(a), "r"(bytes) : "memory");
}
__device__ __forceinline__ void bulk_cp(uint32_t dst, const void* src, uint32_t bytes, uint32_t mbar) {
    asm volatile("cp.async.bulk.shared::cta.global.mbarrier::complete_tx::bytes [%0], [%1], %2, [%3];"
                 :: "r"(dst), "l"(src), "r"(bytes), "r"(mbar) : "memory");
}
#define MBAR_WAIT(addr, par) do { \
    uint32_t _m = (addr), _p = (par), _d; \
    asm volatile("{\n\t.reg .pred p;\n\tmbarrier.try_wait.parity.acquire.cta.shared::cta.b64 p, [%1], %2;\n\tselp.b32 %0, 1, 0, p;\n\t}" \
        : "=r"(_d) : "r"(_m), "r"(_p) : "memory"); \
    if (!_d) { \
        asm volatile("{\n\t.reg .pred P1;\n\tWL%=:\n\tmbarrier.try_wait.parity.acquire.cta.shared::cta.b64 P1, [%0], %1, 0x989680;\n\t@P1 bra.uni WD%=;\n\tbra.uni WL%=;\n\tWD%=:\n\t}" \
            :: "r"(_m), "r"(_p) : "memory"); \
    } } while (0)

// ---- JAX threefry2x32 (20 rounds) ----
__device__ __forceinline__ uint2 tf2x32(unsigned k0, unsigned k1, unsigned x0, unsigned x1) {
    unsigned ks2 = k0 ^ k1 ^ 0x1BD11BDAu;
    x0 += k0; x1 += k1;
#define TFR(r) { x0 += x1; x1 = (x1 << (r)) | (x1 >> (32 - (r))); x1 ^= x0; }
    TFR(13) TFR(15) TFR(26) TFR(6)
    x0 += k1;  x1 += ks2 + 1u;
    TFR(17) TFR(29) TFR(16) TFR(24)
    x0 += ks2; x1 += k0 + 2u;
    TFR(13) TFR(15) TFR(26) TFR(6)
    x0 += k0;  x1 += k1 + 3u;
    TFR(17) TFR(29) TFR(16) TFR(24)
    x0 += k1;  x1 += ks2 + 4u;
    TFR(13) TFR(15) TFR(26) TFR(6)
    x0 += ks2; x1 += k0 + 5u;
#undef TFR
    return make_uint2(x0, x1);
}

__global__ void prep_pack(const float* __restrict__ W_enc,
                          const float* __restrict__ W_sh,
                          const float* __restrict__ W_r1) {
    const int i = blockIdx.x * blockDim.x + threadIdx.x;
    if (i < 32 * 128 * 2) {
        const int j = i & 1, c = (i >> 1) & 127, kp = i >> 8;
        const int k = 2 * kp + j;
        g_Wenc[i] = (k < DXX) ? W_enc[k * 128 + c] : 0.f;
    }
    const int i2 = i - 32 * 128 * 2;
    if (i2 >= 0 && i2 < EXP * 16384) {
        const int e = i2 >> 14, r = i2 & 16383;
        const int k = r >> 7, c = r & 127;          // W_sh[e][k][c]
        const float val = W_sh[e * 16384 + k * 128 + c];
        const __nv_bfloat16 h = __float2bfloat16(val);
        const __nv_bfloat16 m = __float2bfloat16(val - __bfloat162float(h));
        g_WT[(e * 2 + 0) * (128 * 136) + c * 136 + k] = h;
        g_WT[(e * 2 + 1) * (128 * 136) + c * 136 + k] = m;
    }
    const int i3 = i - (32 * 128 * 2 + EXP * 16384);
    if (i3 >= 0 && i3 < EXP * KK1 * 64) {
        const int e = i3 / (KK1 * 64), r = i3 % (KK1 * 64);
        const int kp = r >> 6, c = r & 63;
        const int k0 = 2 * kp, k1 = 2 * kp + 1;
        const float w0 = (k0 < 155) ? W_r1[e * 155 * 64 + k0 * 64 + c] : 0.f;
        const float w1 = (k1 < 155) ? W_r1[e * 155 * 64 + k1 * 64 + c] : 0.f;
        unsigned b0, b1;
        { __nv_bfloat16 t = __float2bfloat16(w0); b0 = *(unsigned short*)&t; }
        { __nv_bfloat16 t = __float2bfloat16(w1); b1 = *(unsigned short*)&t; }
        g_Wr1b[i3] = b0 | (b1 << 16);
    }
}

__global__ void __launch_bounds__(NTH, 1)
nerf_fused(const float* __restrict__ x,
           const float* __restrict__ b_enc,
           const float* __restrict__ b_sh,
           const float* __restrict__ w_sig, const float* __restrict__ b_sig,
           const float* __restrict__ b_r1,
           const float* __restrict__ W_r2,  const float* __restrict__ b_r2,
           float* __restrict__ out, int n)
{
    extern __shared__ char smc[];
    const int tid = threadIdx.x;
    const int n0  = blockIdx.x * TP;
    const int wp  = tid >> 5, l = tid & 31;
    const uint32_t sbase = (uint32_t)__cvta_generic_to_shared(smc);

    float* s_g    = (float*)(smc + SM_G);
    float* s_part = (float*)(smc + SM_PART);
    float* sbias  = (float*)(smc + SM_SBIAS);
    float* sigw   = (float*)(smc + SM_SIGW);
    float* sbexp  = (float*)(smc + SM_BEXP);
    float* sbsig  = (float*)(smc + SM_BSIG);
    float* s_upd  = (float*)(smc + SM_UPD);
    ull*   shb    = (ull*)(smc + SM_SHB);
    __nv_bfloat16* wr2s = (__nv_bfloat16*)(smc + SM_WR2);
    float* br2s   = (float*)(smc + SM_BR2);
    const uint32_t mbar = sbase + SM_MBAR;

    // ---------- init mbarrier + launch expert-0 B-tile bulk copy ----------
    if (tid == 0) {
        mbar_init(mbar, 1);
        mbar_expect(mbar, B_BYTES);
        bulk_cp(sbase + SM_BH, (const char*)g_WT, B_BYTES, mbar);
    }

    // ---------- Phase A: PE into x_tp (overlay on shb) / vd ----------
    if (tid < 384) {
        const int p = tid / 3, c = tid % 3;
        float xc = 0.f, vc = 0.f;
        if (n0 + p < n) {
            xc = x[(n0 + p) * 6 + c];
            vc = x[(n0 + p) * 6 + 3 + c];
        }
        float* xf = (float*)(smc + SM_SHB);
        float* vf = (float*)(smc + SM_VD);
#define PUTX(k, v) xf[((k) >> 1) * 258 + 2 * p + ((k) & 1)] = (v)
#define PUTV(k, v) vf[((k) >> 1) * 258 + 2 * p + ((k) & 1)] = (v)
        PUTX(c, xc);
        float f = 1.f;
#pragma unroll
        for (int i = 0; i < 10; i++) {
            float sv, cv; sincosf(f * xc, &sv, &cv);
            PUTX(3 + 3 * i + c, sv);
            PUTX(33 + 3 * i + c, cv);
            f *= 2.f;
        }
        PUTV(c, vc);
        f = 1.f;
#pragma unroll
        for (int i = 0; i < 4; i++) {
            float sv, cv; sincosf(f * vc, &sv, &cv);
            PUTV(3 + 3 * i + c, sv);
            PUTV(15 + 3 * i + c, cv);
            f *= 2.f;
        }
#undef PUTX
#undef PUTV
    }
    if (tid < 128) {
        ((float*)(smc + SM_SHB))[31 * 258 + 2 * tid + 1] = 0.f;  // x pad k=63
        ((float*)(smc + SM_VD))[13 * 258 + 2 * tid + 1] = 0.f;   // vd pad k=27
        sigw[tid] = w_sig[tid];
    }
    // ---------- stage W_r2 (bf16) + b_r2 into smem ----------
    for (int i = tid; i < EXP * HDIM * 3; i += NTH)
        wr2s[i] = __float2bfloat16(W_r2[i]);
    if (tid < 24) br2s[tid] = b_r2[tid];
    // ---------- Gumbel (JAX threefry, partitionable) ----------
#pragma unroll
    for (int idx = tid; idx < TP * EXP; idx += NTH) {
        const int p = idx >> 3;
        const unsigned f = (unsigned)(n0 + p) * 8u + (unsigned)(idx & 7);
        const uint2 r = tf2x32(0u, 42u, 0u, f);
        const unsigned bits = r.x ^ r.y;
        const float u = __uint_as_float((bits >> 9) | 0x3f800000u) - 1.0f;
        s_g[idx] = -logf(-logf(u + 1e-20f) + 1e-20f);
    }
    __syncthreads();

    // ---------- Phase B: y = relu(pe @ W_enc + b); 16 warps x 8 cols x 128 pts ----------
    {
        const int c0 = wp * 8;
        ull acc[8][4];
#pragma unroll
        for (int j = 0; j < 8; j++)
#pragma unroll
            for (int q = 0; q < 4; q++) acc[j][q] = 0ull;
        const ulonglong2* wE = (const ulonglong2*)g_Wenc + (c0 >> 1);
        const ull* xr = (const ull*)(smc + SM_SHB);
#pragma unroll 2
        for (int kp = 0; kp < 32; kp++) {
            ull a[4];
#pragma unroll
            for (int q = 0; q < 4; q++) a[q] = xr[kp * 129 + q * 32 + l];
            const ulonglong2 q0 = wE[kp * 64 + 0], q1 = wE[kp * 64 + 1];
            const ulonglong2 q2 = wE[kp * 64 + 2], q3 = wE[kp * 64 + 3];
            const ull w[8] = {q0.x, q0.y, q1.x, q1.y, q2.x, q2.y, q3.x, q3.y};
#pragma unroll
            for (int j = 0; j < 8; j++)
#pragma unroll
                for (int q = 0; q < 4; q++) ffma2(acc[j][q], a[q], w[j]);
        }
        __syncthreads();   // x_tp reads complete before shb-region reuse (winner stores)
#pragma unroll
        for (int j = 0; j < 8; j++) {
            const int col = c0 + j;
            const float bc = b_enc[col];
#pragma unroll
            for (int q = 0; q < 4; q++) {
                const float2 f2 = unpack2(acc[j][q]);
                const float v = fmaxf(f2.x + f2.y + bc, 0.f);
                const int p = l + 32 * q;
                const __nv_bfloat16 h = __float2bfloat16(v);
                const __nv_bfloat16 m = __float2bfloat16(v - __bfloat162float(h));
                *(__nv_bfloat16*)(smc + SM_AH + (p * 136 + col) * 2) = h;
                *(__nv_bfloat16*)(smc + SM_AM + (p * 136 + col) * 2) = m;
            }
        }
    }

    // ---------- MMA fragment address bases (warp grid 4m x 4n, tile 32x32) ----------
    const int wm = wp >> 2, wn = wp & 3;
    const int m0 = wm * 32, nn0 = wn * 32;
    const uint32_t aOff = ((m0 + (l & 15)) * 136 + (l >> 4) * 8) * 2;
    const uint32_t aH0 = sbase + SM_AH + aOff, aH1 = aH0 + 16 * 272;
    const uint32_t aM0 = sbase + SM_AM + aOff, aM1 = aM0 + 16 * 272;
    const uint32_t bOff = ((nn0 + (l & 7) + ((l >> 4) & 1) * 8) * 136 + ((l >> 3) & 1) * 8) * 2;
    const uint32_t bH0 = sbase + SM_BH + bOff, bH1 = bH0 + 16 * 272;
    const uint32_t bM0 = sbase + SM_BM + bOff, bM1 = bM0 + 16 * 272;

    float best_sc = 0.f, best_sig = 0.f;
    int best_e = 0;
    const float bsig0 = b_sig[0];

    if (tid < 128) sbias[tid] = b_sh[tid];
    __syncthreads();   // A tiles + sbias visible

    // ---------- Expert loop ----------
    for (int e = 0; e < EXP; e++) {
        MBAR_WAIT(mbar, e & 1);   // wait for this expert's B tiles

        float acc[2][4][4];
#pragma unroll
        for (int mf = 0; mf < 2; mf++)
#pragma unroll
            for (int nf = 0; nf < 4; nf++)
#pragma unroll
                for (int i = 0; i < 4; i++) acc[mf][nf][i] = 0.f;

#pragma unroll
        for (int kc = 0; kc < 8; kc++) {
            uint32_t ah[2][4], am[2][4], bh[2][4], bm[2][4];
            ldsm4(ah[0], aH0 + kc * 32);  ldsm4(ah[1], aH1 + kc * 32);
            ldsm4(am[0], aM0 + kc * 32);  ldsm4(am[1], aM1 + kc * 32);
            ldsm4(bh[0], bH0 + kc * 32);  ldsm4(bh[1], bH1 + kc * 32);
            ldsm4(bm[0], bM0 + kc * 32);  ldsm4(bm[1], bM1 + kc * 32);
#pragma unroll
            for (int mf = 0; mf < 2; mf++)
#pragma unroll
                for (int np = 0; np < 2; np++) {
                    mma16816(acc[mf][np*2+0], ah[mf], &bh[np][0]);
                    mma16816(acc[mf][np*2+1], ah[mf], &bh[np][2]);
                    mma16816(acc[mf][np*2+0], ah[mf], &bm[np][0]);
                    mma16816(acc[mf][np*2+1], ah[mf], &bm[np][2]);
                    mma16816(acc[mf][np*2+0], am[mf], &bh[np][0]);
                    mma16816(acc[mf][np*2+1], am[mf], &bh[np][2]);
                }
        }

        // epilogue: bias+relu into acc, sigma partials
        float part[4] = {0.f, 0.f, 0.f, 0.f};
#pragma unroll
        for (int mf = 0; mf < 2; mf++)
#pragma unroll
            for (int nf = 0; nf < 4; nf++) {
                const int c0 = nn0 + nf * 8 + (l & 3) * 2;
                const float b0 = sbias[c0], b1 = sbias[c0 + 1];
                const float w0 = sigw[c0],  w1 = sigw[c0 + 1];
                const float v00 = fmaxf(acc[mf][nf][0] + b0, 0.f);
                const float v01 = fmaxf(acc[mf][nf][1] + b1, 0.f);
                const float v10 = fmaxf(acc[mf][nf][2] + b0, 0.f);
                const float v11 = fmaxf(acc[mf][nf][3] + b1, 0.f);
                acc[mf][nf][0] = v00; acc[mf][nf][1] = v01;
                acc[mf][nf][2] = v10; acc[mf][nf][3] = v11;
                part[mf*2+0] += v00 * w0 + v01 * w1;
                part[mf*2+1] += v10 * w0 + v11 * w1;
            }
#pragma unroll
        for (int i = 0; i < 4; i++) {
            part[i] += __shfl_xor_sync(0xffffffffu, part[i], 1);
            part[i] += __shfl_xor_sync(0xffffffffu, part[i], 2);
        }
        if ((l & 3) == 0) {
#pragma unroll
            for (int mf = 0; mf < 2; mf++)
#pragma unroll
                for (int hf = 0; hf < 2; hf++)
                    s_part[wn * 128 + m0 + mf * 16 + (l >> 2) + hf * 8] = part[mf*2+hf];
        }
        __syncthreads();    // all ldsm/mma done -> B buffer reusable

        // launch next expert's B bulk copy (overlaps gating + winner store)
        if (tid == 0 && e < EXP - 1) {
            mbar_expect(mbar, B_BYTES);
            bulk_cp(sbase + SM_BH, (const char*)g_WT + (size_t)(e + 1) * B_BYTES, B_BYTES, mbar);
        }

        if (tid < 128) {
            const float t = s_part[tid] + s_part[128 + tid] + s_part[256 + tid]
                          + s_part[384 + tid] + bsig0;
            const float sg = fmaxf(t, 0.f) + log1pf(expf(-fabsf(t)));  // softplus
            const float sc = logf(sg + 1e-10f) / 0.166667f + s_g[tid * 8 + e];
            const bool win = (e == 0) || (sc > best_sc);
            if (win) { best_sc = sc; best_sig = sg; best_e = e; }
            s_upd[tid] = win ? 1.f : 0.f;
        }
        __syncthreads();

        // winner shape store (transposed-pair layout for C3')
#pragma unroll
        for (int mf = 0; mf < 2; mf++) {
            const int rA = m0 + mf * 16 + (l >> 2);
            const bool wA = (s_upd[rA] != 0.f), wB = (s_upd[rA + 8] != 0.f);
#pragma unroll
            for (int nf = 0; nf < 4; nf++) {
                const int cp_i = wn * 16 + nf * 4 + (l & 3);
                if (wA) shb[cp_i * 129 + rA]     = pack2(acc[mf][nf][0], acc[mf][nf][1]);
                if (wB) shb[cp_i * 129 + rA + 8] = pack2(acc[mf][nf][2], acc[mf][nf][3]);
            }
        }
        if (tid < 128 && e < EXP - 1) sbias[tid] = b_sh[(e + 1) * 128 + tid];
        __syncthreads();
    }

    if (tid < 128) { sbexp[tid] = (float)best_e; sbsig[tid] = best_sig; }
    __syncthreads();

    // ---------- C3': h = relu([shape | vd] @ W_r1[winner] + b); 16 warps x 8 pts ----------
    float* s_h = (float*)(smc + SM_AH);   // overlay on dead A tiles: [128][66]
    {
        const int p0 = wp * 8;
        int we[8];
        const uint2* w1[8];
        ull acc[8][2];
#pragma unroll
        for (int p = 0; p < 8; p++) {
            we[p] = (int)sbexp[p0 + p];
            w1[p] = (const uint2*)(g_Wr1b + we[p] * (KK1 * 64)) + l;
            acc[p][0] = 0ull; acc[p][1] = 0ull;
        }
#pragma unroll 2
        for (int kp = 0; kp < 64; kp++) {
#pragma unroll
            for (int p = 0; p < 8; p++) {
                const uint2 q = w1[p][kp * 32];
                const ull a = shb[kp * 129 + p0 + p];
                ffma2(acc[p][0], a, bf2w(q.x));
                ffma2(acc[p][1], a, bf2w(q.y));
            }
        }
        const ull* vdp = (const ull*)(smc + SM_VD);
#pragma unroll
        for (int kp = 64; kp < KK1; kp++) {
#pragma unroll
            for (int p = 0; p < 8; p++) {
                const uint2 q = w1[p][kp * 32];
                const ull a = vdp[(kp - 64) * 129 + p0 + p];
                ffma2(acc[p][0], a, bf2w(q.x));
                ffma2(acc[p][1], a, bf2w(q.y));
            }
        }
#pragma unroll
        for (int p = 0; p < 8; p++) {
            const float2 bv = *(const float2*)(b_r1 + we[p] * HDIM + l * 2);
            const float2 f0 = unpack2(acc[p][0]), f1 = unpack2(acc[p][1]);
            const float h0 = fmaxf(f0.x + f0.y + bv.x, 0.f);
            const float h1 = fmaxf(f1.x + f1.y + bv.y, 0.f);
            *(ull*)(s_h + (p0 + p) * 66 + l * 2) = pack2(h0, h1);
        }
    }
    __syncthreads();

    // ---------- C4': rgb = sigmoid(h @ W_r2[winner] + b) -> out ----------
    if (tid < 384) {
        const int p = tid % 128, c = tid / 128;
        const int we = (int)sbexp[p];
        float acc = br2s[we * 3 + c];
        const float* hp = s_h + p * 66;
        const __nv_bfloat16* w2 = wr2s + we * (HDIM * 3) + c;
#pragma unroll
        for (int k = 0; k < HDIM; k++)
            acc = fmaf(hp[k], __bfloat162float(w2[k * 3]), acc);
        if (n0 + p < n)
            out[(n0 + p) * 4 + c] = 1.f / (1.f + expf(-acc));
    }
    if (tid < 128 && n0 + tid < n)
        out[(n0 + tid) * 4 + 3] = sbsig[tid];
}

extern "C" void kernel_launch(void* const* d_in, const int* in_sizes, int n_in,
                              void* d_out, int out_size) {
    const float* x     = (const float*)d_in[0];
    const float* W_enc = (const float*)d_in[1];
    const float* b_enc = (const float*)d_in[2];
    const float* W_sh  = (const float*)d_in[3];
    const float* b_sh  = (const float*)d_in[4];
    const float* w_sig = (const float*)d_in[5];
    const float* b_sig = (const float*)d_in[6];
    const float* W_r1  = (const float*)d_in[7];
    const float* b_r1  = (const float*)d_in[8];
    const float* W_r2  = (const float*)d_in[9];
    const float* b_r2  = (const float*)d_in[10];
    float* out = (float*)d_out;

    const int n = in_sizes[0] / 6;
    const int blocks = (n + TP - 1) / TP;

    const int prep_elems = 32*128*2 + EXP*16384 + EXP*KK1*64;
    prep_pack<<<(prep_elems + 255) / 256, 256>>>(W_enc, W_sh, W_r1);

    cudaFuncSetAttribute(nerf_fused, cudaFuncAttributeMaxDynamicSharedMemorySize, SM_TOTAL);
    nerf_fused<<<blocks, NTH, SM_TOTAL>>>(x, b_enc, b_sh, w_sig, b_sig,
                                          b_r1, W_r2, b_r2, out, n);
}